// round 1
// baseline (speedup 1.0000x reference)
#include <cuda_runtime.h>

// ---------------- static scratch (no dynamic allocation allowed) ------------
#define MAXN 50016
#define MAXE 800000

__device__ float g_H1[MAXN * 64];   // layer-1 features x@W1
__device__ float g_as1[MAXN * 4];   // alpha_src layer1 per head
__device__ float g_ad1[MAXN * 4];   // alpha_dst layer1 per head
__device__ float g_X2[MAXN * 64];   // elu(gat1 output) = input to layer2
__device__ float g_H2[MAXN * 32];   // layer-2 features X2@W2
__device__ float g_as2[MAXN];
__device__ float g_ad2[MAXN];
__device__ int   g_deg[MAXN];
__device__ int   g_rowptr[MAXN + 1];
__device__ int   g_wpos[MAXN + 1];
__device__ int   g_csrsrc[MAXE];
__device__ int   g_bsums[64];
__device__ int   g_boffs[64];

// ---------------- CSR build -------------------------------------------------
__global__ void k_zero_deg(int N) {
    int i = blockIdx.x * blockDim.x + threadIdx.x;
    if (i < N) g_deg[i] = 0;
}

__global__ void k_hist(const int* __restrict__ ei, int E) {
    int e = blockIdx.x * blockDim.x + threadIdx.x;
    if (e < E) atomicAdd(&g_deg[ei[E + e]], 1);
}

__global__ void k_scan_block(int N) {
    __shared__ int sh[1024];
    int t = threadIdx.x;
    int i = blockIdx.x * 1024 + t;
    int v = (i < N) ? g_deg[i] : 0;
    sh[t] = v;
    __syncthreads();
    for (int off = 1; off < 1024; off <<= 1) {
        int u = (t >= off) ? sh[t - off] : 0;
        __syncthreads();
        sh[t] += u;
        __syncthreads();
    }
    if (i < N) g_rowptr[i + 1] = sh[t];
    if (t == 1023) g_bsums[blockIdx.x] = sh[1023];
}

__global__ void k_scan_sums(int nb) {
    if (threadIdx.x == 0) {
        int run = 0;
        for (int b = 0; b < nb; ++b) { g_boffs[b] = run; run += g_bsums[b]; }
    }
}

__global__ void k_scan_add(int N) {
    int t = threadIdx.x;
    int i = blockIdx.x * 1024 + t;
    if (i < N) {
        int v = g_rowptr[i + 1] + g_boffs[blockIdx.x];
        g_rowptr[i + 1] = v;
        g_wpos[i + 1] = v;
    }
    if (blockIdx.x == 0 && t == 0) { g_rowptr[0] = 0; g_wpos[0] = 0; }
}

__global__ void k_fill(const int* __restrict__ ei, int E) {
    int e = blockIdx.x * blockDim.x + threadIdx.x;
    if (e < E) {
        int src = ei[e];
        int dst = ei[E + e];
        int p = atomicAdd(&g_wpos[dst], 1);
        g_csrsrc[p] = src;
    }
}

// ---------------- GEMM 1: H1 = x[N,128] @ W1[128,64] -----------------------
// block = 256 threads, tile = 128 nodes. thread covers 4 nodes x 8 cols.
__global__ void k_gemm1(const float* __restrict__ x, const float* __restrict__ W1, int N) {
    __shared__ float Wsh[128 * 64];   // 32 KB
    __shared__ float xs[128][17];     // 16-wide k tile + pad
    int t = threadIdx.x;
    int n0 = blockIdx.x * 128;
    for (int i = t; i < 128 * 64; i += 256) Wsh[i] = W1[i];

    int ng = t >> 3;   // 0..31 node group (4 nodes each)
    int cg = t & 7;    // 0..7 col group (8 cols each)
    float acc[4][8];
#pragma unroll
    for (int r = 0; r < 4; ++r)
#pragma unroll
        for (int j = 0; j < 8; ++j) acc[r][j] = 0.f;

    for (int kt = 0; kt < 128; kt += 16) {
        __syncthreads();
        for (int i = t; i < 128 * 16; i += 256) {
            int n = i >> 4, kk = i & 15;
            int gn = n0 + n;
            xs[n][kk] = (gn < N) ? x[gn * 128 + kt + kk] : 0.f;
        }
        __syncthreads();
#pragma unroll
        for (int kk = 0; kk < 16; ++kk) {
            float wv[8];
#pragma unroll
            for (int j = 0; j < 8; ++j) wv[j] = Wsh[(kt + kk) * 64 + cg * 8 + j];
#pragma unroll
            for (int r = 0; r < 4; ++r) {
                float xv = xs[ng * 4 + r][kk];
#pragma unroll
                for (int j = 0; j < 8; ++j) acc[r][j] = fmaf(xv, wv[j], acc[r][j]);
            }
        }
    }
#pragma unroll
    for (int r = 0; r < 4; ++r) {
        int gn = n0 + ng * 4 + r;
        if (gn < N) {
            float4* dst = reinterpret_cast<float4*>(&g_H1[gn * 64 + cg * 8]);
            dst[0] = make_float4(acc[r][0], acc[r][1], acc[r][2], acc[r][3]);
            dst[1] = make_float4(acc[r][4], acc[r][5], acc[r][6], acc[r][7]);
        }
    }
}

// ---------------- per-node alpha_src / alpha_dst (layer 1) ------------------
__global__ void k_alphas1(const float* __restrict__ a_src, const float* __restrict__ a_dst, int N) {
    __shared__ float as_sh[64], ad_sh[64];
    if (threadIdx.x < 64) { as_sh[threadIdx.x] = a_src[threadIdx.x]; ad_sh[threadIdx.x] = a_dst[threadIdx.x]; }
    __syncthreads();
    int n = blockIdx.x * blockDim.x + threadIdx.x;
    if (n >= N) return;
    const float4* hr = reinterpret_cast<const float4*>(&g_H1[n * 64]);
    float as[4] = {0, 0, 0, 0}, ad[4] = {0, 0, 0, 0};
#pragma unroll
    for (int q = 0; q < 16; ++q) {
        float4 h = hr[q];
        int c = q * 4;
        int hd = q >> 2;
        as[hd] += h.x * as_sh[c] + h.y * as_sh[c + 1] + h.z * as_sh[c + 2] + h.w * as_sh[c + 3];
        ad[hd] += h.x * ad_sh[c] + h.y * ad_sh[c + 1] + h.z * ad_sh[c + 2] + h.w * ad_sh[c + 3];
    }
#pragma unroll
    for (int hd = 0; hd < 4; ++hd) { g_as1[n * 4 + hd] = as[hd]; g_ad1[n * 4 + hd] = ad[hd]; }
}

// ---------------- layer-1 aggregation: warp/node, online softmax ------------
__global__ void k_agg1(const float* __restrict__ b1, int N) {
    int gw = (blockIdx.x * blockDim.x + threadIdx.x) >> 5;
    if (gw >= N) return;
    int lane = threadIdx.x & 31;
    int i = gw;
    int beg = g_rowptr[i], end = g_rowptr[i + 1];
    int ch = lane * 2;
    int head = ch >> 4;
    float adv = g_ad1[i * 4 + head];

    float m = -1e30f, s = 0.f, a0 = 0.f, a1 = 0.f;
    int srcN = 0; float asvN = 0.f;
    if (beg < end) { srcN = g_csrsrc[beg]; asvN = __ldg(&g_as1[srcN * 4 + head]); }
    for (int p = beg; p < end; ++p) {
        int src = srcN; float asv = asvN;
        if (p + 1 < end) { srcN = g_csrsrc[p + 1]; asvN = __ldg(&g_as1[srcN * 4 + head]); }
        float2 hv = *reinterpret_cast<const float2*>(&g_H1[src * 64 + ch]);
        float e = asv + adv;
        e = (e > 0.f) ? e : 0.2f * e;
        float mn = fmaxf(m, e);
        float corr = __expf(m - mn);
        float w = __expf(e - mn);
        s = s * corr + w;
        a0 = a0 * corr + w * hv.x;
        a1 = a1 * corr + w * hv.y;
        m = mn;
    }
    float inv = 1.f / (s + 1e-16f);
    float o0 = a0 * inv + b1[ch];
    float o1 = a1 * inv + b1[ch + 1];
    o0 = (o0 > 0.f) ? o0 : expm1f(o0);   // elu
    o1 = (o1 > 0.f) ? o1 : expm1f(o1);
    *reinterpret_cast<float2*>(&g_X2[i * 64 + ch]) = make_float2(o0, o1);
}

// ---------------- GEMM 2: H2 = X2[N,64] @ W2[64,32] -------------------------
// block = 128 threads, tile = 128 nodes. thread covers 4 nodes x 8 cols.
__global__ void k_gemm2(const float* __restrict__ W2, int N) {
    __shared__ float Wsh[64 * 32];    // 8 KB
    __shared__ float xs[128][65];     // full 64-wide k, padded
    int t = threadIdx.x;
    int n0 = blockIdx.x * 128;
    for (int i = t; i < 64 * 32; i += 128) Wsh[i] = W2[i];
    for (int i = t; i < 128 * 64; i += 128) {
        int n = i >> 6, k = i & 63;
        int gn = n0 + n;
        xs[n][k] = (gn < N) ? g_X2[gn * 64 + k] : 0.f;
    }
    __syncthreads();
    int ng = t >> 2;   // 0..31 (4 nodes each)
    int cg = t & 3;    // 0..3 (8 cols each)
    float acc[4][8];
#pragma unroll
    for (int r = 0; r < 4; ++r)
#pragma unroll
        for (int j = 0; j < 8; ++j) acc[r][j] = 0.f;
#pragma unroll 4
    for (int k = 0; k < 64; ++k) {
        float wv[8];
#pragma unroll
        for (int j = 0; j < 8; ++j) wv[j] = Wsh[k * 32 + cg * 8 + j];
#pragma unroll
        for (int r = 0; r < 4; ++r) {
            float xv = xs[ng * 4 + r][k];
#pragma unroll
            for (int j = 0; j < 8; ++j) acc[r][j] = fmaf(xv, wv[j], acc[r][j]);
        }
    }
#pragma unroll
    for (int r = 0; r < 4; ++r) {
        int gn = n0 + ng * 4 + r;
        if (gn < N) {
            float4* dst = reinterpret_cast<float4*>(&g_H2[gn * 32 + cg * 8]);
            dst[0] = make_float4(acc[r][0], acc[r][1], acc[r][2], acc[r][3]);
            dst[1] = make_float4(acc[r][4], acc[r][5], acc[r][6], acc[r][7]);
        }
    }
}

// ---------------- per-node alpha_src / alpha_dst (layer 2) ------------------
__global__ void k_alphas2(const float* __restrict__ a_src, const float* __restrict__ a_dst, int N) {
    __shared__ float as_sh[32], ad_sh[32];
    if (threadIdx.x < 32) { as_sh[threadIdx.x] = a_src[threadIdx.x]; ad_sh[threadIdx.x] = a_dst[threadIdx.x]; }
    __syncthreads();
    int n = blockIdx.x * blockDim.x + threadIdx.x;
    if (n >= N) return;
    const float4* hr = reinterpret_cast<const float4*>(&g_H2[n * 32]);
    float as = 0.f, ad = 0.f;
#pragma unroll
    for (int q = 0; q < 8; ++q) {
        float4 h = hr[q];
        int c = q * 4;
        as += h.x * as_sh[c] + h.y * as_sh[c + 1] + h.z * as_sh[c + 2] + h.w * as_sh[c + 3];
        ad += h.x * ad_sh[c] + h.y * ad_sh[c + 1] + h.z * ad_sh[c + 2] + h.w * ad_sh[c + 3];
    }
    g_as2[n] = as;
    g_ad2[n] = ad;
}

// ---------------- layer-2 aggregation: warp/node, 1 head, 32 channels -------
__global__ void k_agg2(const float* __restrict__ b2, float* __restrict__ out, int N) {
    int gw = (blockIdx.x * blockDim.x + threadIdx.x) >> 5;
    if (gw >= N) return;
    int lane = threadIdx.x & 31;
    int i = gw;
    int beg = g_rowptr[i], end = g_rowptr[i + 1];
    float adv = g_ad2[i];

    float m = -1e30f, s = 0.f, a = 0.f;
    int srcN = 0; float asvN = 0.f;
    if (beg < end) { srcN = g_csrsrc[beg]; asvN = __ldg(&g_as2[srcN]); }
    for (int p = beg; p < end; ++p) {
        int src = srcN; float asv = asvN;
        if (p + 1 < end) { srcN = g_csrsrc[p + 1]; asvN = __ldg(&g_as2[srcN]); }
        float hv = g_H2[src * 32 + lane];
        float e = asv + adv;
        e = (e > 0.f) ? e : 0.2f * e;
        float mn = fmaxf(m, e);
        float corr = __expf(m - mn);
        float w = __expf(e - mn);
        s = s * corr + w;
        a = a * corr + w * hv;
        m = mn;
    }
    float inv = 1.f / (s + 1e-16f);
    out[i * 32 + lane] = a * inv + b2[lane];
}

// ---------------- launch -----------------------------------------------------
extern "C" void kernel_launch(void* const* d_in, const int* in_sizes, int n_in,
                              void* d_out, int out_size) {
    const float* x      = (const float*)d_in[0];
    const int*   ei     = (const int*)  d_in[1];
    const float* W1     = (const float*)d_in[2];
    const float* a_src1 = (const float*)d_in[3];
    const float* a_dst1 = (const float*)d_in[4];
    const float* b1     = (const float*)d_in[5];
    const float* W2     = (const float*)d_in[6];
    const float* a_src2 = (const float*)d_in[7];
    const float* a_dst2 = (const float*)d_in[8];
    const float* b2     = (const float*)d_in[9];

    int N = in_sizes[0] / 128;
    int E = in_sizes[1] / 2;
    int nb = (N + 1023) / 1024;

    // CSR build (by dst)
    k_zero_deg<<<(N + 255) / 256, 256>>>(N);
    k_hist<<<(E + 255) / 256, 256>>>(ei, E);
    k_scan_block<<<nb, 1024>>>(N);
    k_scan_sums<<<1, 32>>>(nb);
    k_scan_add<<<nb, 1024>>>(N);
    k_fill<<<(E + 255) / 256, 256>>>(ei, E);

    // layer 1
    k_gemm1<<<(N + 127) / 128, 256>>>(x, W1, N);
    k_alphas1<<<(N + 255) / 256, 256>>>(a_src1, a_dst1, N);
    k_agg1<<<(N * 32 + 255) / 256, 256>>>(b1, N);

    // layer 2
    k_gemm2<<<(N + 127) / 128, 128>>>(W2, N);
    k_alphas2<<<(N + 255) / 256, 256>>>(a_src2, a_dst2, N);
    k_agg2<<<(N * 32 + 255) / 256, 256>>>(b2, (float*)d_out, N);
}

// round 2
// speedup vs baseline: 1.1203x; 1.1203x over previous
#include <cuda_runtime.h>

// ---------------- static scratch (no dynamic allocation allowed) ------------
#define MAXN 50016
#define MAXE 800000

__device__ float g_H1[MAXN * 64];   // layer-1 features x@W1
__device__ float g_as1[MAXN * 4];   // alpha_src layer1 per head
__device__ float g_ad1[MAXN * 4];   // alpha_dst layer1 per head
__device__ float g_X2[MAXN * 64];   // elu(gat1 output) = input to layer2
__device__ float g_H2[MAXN * 32];   // layer-2 features X2@W2
__device__ float g_as2[MAXN];
__device__ float g_ad2[MAXN];
__device__ int   g_deg[MAXN];       // zero-initialized at load; re-zeroed by k_scan_add each run
__device__ int   g_rowptr[MAXN + 1];
__device__ int   g_wpos[MAXN + 1];
__device__ int   g_csrsrc[MAXE];
__device__ int   g_bsums[64];
__device__ int   g_boffs[64];

// ---------------- L1: fused GEMM1 (+alpha epilogue) ⊕ edge histogram --------
// gemm blocks: 256 threads, tile = 128 nodes, thread = 4 nodes x 8 cols.
// hist blocks: grid-stride atomicAdd over dst.
__global__ void k_gemm1_hist(const float* __restrict__ x, const float* __restrict__ W1,
                             const float* __restrict__ a_src, const float* __restrict__ a_dst,
                             const int* __restrict__ ei, int N, int E, int gemmBlocks) {
    __shared__ float Wsh[128 * 64];   // 32 KB
    __shared__ float xs[128][17];     // 16-wide k tile + pad

    if (blockIdx.x >= gemmBlocks) {
        // ---- histogram part (independent of GEMM) ----
        int nb = gridDim.x - gemmBlocks;
        int stride = nb * blockDim.x;
        for (int e = (blockIdx.x - gemmBlocks) * blockDim.x + threadIdx.x; e < E; e += stride)
            atomicAdd(&g_deg[ei[E + e]], 1);
        return;
    }

    int t = threadIdx.x;
    int n0 = blockIdx.x * 128;
    for (int i = t; i < 128 * 64; i += 256) Wsh[i] = W1[i];

    int ng = t >> 3;   // 0..31 node group (4 nodes each)
    int cg = t & 7;    // 0..7 col group (8 cols each)
    float acc[4][8];
#pragma unroll
    for (int r = 0; r < 4; ++r)
#pragma unroll
        for (int j = 0; j < 8; ++j) acc[r][j] = 0.f;

    for (int kt = 0; kt < 128; kt += 16) {
        __syncthreads();
        for (int i = t; i < 128 * 16; i += 256) {
            int n = i >> 4, kk = i & 15;
            int gn = n0 + n;
            xs[n][kk] = (gn < N) ? x[gn * 128 + kt + kk] : 0.f;
        }
        __syncthreads();
#pragma unroll
        for (int kk = 0; kk < 16; ++kk) {
            float wv[8];
#pragma unroll
            for (int j = 0; j < 8; ++j) wv[j] = Wsh[(kt + kk) * 64 + cg * 8 + j];
#pragma unroll
            for (int r = 0; r < 4; ++r) {
                float xv = xs[ng * 4 + r][kk];
#pragma unroll
                for (int j = 0; j < 8; ++j) acc[r][j] = fmaf(xv, wv[j], acc[r][j]);
            }
        }
    }

    // per-thread attention coefficient slices
    float asw[8], adw[8];
#pragma unroll
    for (int j = 0; j < 8; ++j) { asw[j] = __ldg(&a_src[cg * 8 + j]); adw[j] = __ldg(&a_dst[cg * 8 + j]); }

#pragma unroll
    for (int r = 0; r < 4; ++r) {
        int gn = n0 + ng * 4 + r;
        float ps = 0.f, pd = 0.f;
#pragma unroll
        for (int j = 0; j < 8; ++j) { ps = fmaf(acc[r][j], asw[j], ps); pd = fmaf(acc[r][j], adw[j], pd); }
        // combine the two col-groups of this head (lanes t, t^1)
        ps += __shfl_xor_sync(0xffffffffu, ps, 1);
        pd += __shfl_xor_sync(0xffffffffu, pd, 1);
        if (gn < N) {
            float4* dst = reinterpret_cast<float4*>(&g_H1[gn * 64 + cg * 8]);
            dst[0] = make_float4(acc[r][0], acc[r][1], acc[r][2], acc[r][3]);
            dst[1] = make_float4(acc[r][4], acc[r][5], acc[r][6], acc[r][7]);
            if ((cg & 1) == 0) {
                g_as1[gn * 4 + (cg >> 1)] = ps;
                g_ad1[gn * 4 + (cg >> 1)] = pd;
            }
        }
    }
}

// ---------------- CSR scan --------------------------------------------------
__global__ void k_scan_block(int N) {
    __shared__ int sh[1024];
    int t = threadIdx.x;
    int i = blockIdx.x * 1024 + t;
    int v = (i < N) ? g_deg[i] : 0;
    sh[t] = v;
    __syncthreads();
    for (int off = 1; off < 1024; off <<= 1) {
        int u = (t >= off) ? sh[t - off] : 0;
        __syncthreads();
        sh[t] += u;
        __syncthreads();
    }
    if (i < N) g_rowptr[i + 1] = sh[t];
    if (t == 1023) g_bsums[blockIdx.x] = sh[1023];
}

__global__ void k_scan_sums(int nb) {
    int lane = threadIdx.x;            // 32 threads, nb <= 64
    int v1 = (lane < nb) ? g_bsums[lane] : 0;
    int v2 = (lane + 32 < nb) ? g_bsums[lane + 32] : 0;
#pragma unroll
    for (int o = 1; o < 32; o <<= 1) { int u = __shfl_up_sync(0xffffffffu, v1, o); if (lane >= o) v1 += u; }
    int tot1 = __shfl_sync(0xffffffffu, v1, 31);
#pragma unroll
    for (int o = 1; o < 32; o <<= 1) { int u = __shfl_up_sync(0xffffffffu, v2, o); if (lane >= o) v2 += u; }
    int ex1 = __shfl_up_sync(0xffffffffu, v1, 1); if (lane == 0) ex1 = 0;
    int ex2 = __shfl_up_sync(0xffffffffu, v2, 1); if (lane == 0) ex2 = 0;
    if (lane < nb) g_boffs[lane] = ex1;
    if (lane + 32 < nb) g_boffs[lane + 32] = ex2 + tot1;
}

__global__ void k_scan_add(int N) {
    int t = threadIdx.x;
    int i = blockIdx.x * 1024 + t;
    if (i < N) {
        int v = g_rowptr[i + 1] + g_boffs[blockIdx.x];
        g_rowptr[i + 1] = v;
        g_wpos[i + 1] = v;
        g_deg[i] = 0;                  // reset for next replay (device globals start zeroed)
    }
    if (blockIdx.x == 0 && t == 0) { g_rowptr[0] = 0; g_wpos[0] = 0; }
}

__global__ void k_fill(const int* __restrict__ ei, int E) {
    int e = blockIdx.x * blockDim.x + threadIdx.x;
    if (e < E) {
        int src = ei[e];
        int dst = ei[E + e];
        int p = atomicAdd(&g_wpos[dst], 1);
        g_csrsrc[p] = src;
    }
}

// ---------------- layer-1 aggregation: warp/node, online softmax ------------
__global__ void k_agg1(const float* __restrict__ b1, int N) {
    int gw = (blockIdx.x * blockDim.x + threadIdx.x) >> 5;
    if (gw >= N) return;
    int lane = threadIdx.x & 31;
    int i = gw;
    int beg = g_rowptr[i], end = g_rowptr[i + 1];
    int ch = lane * 2;
    int head = ch >> 4;
    float adv = g_ad1[i * 4 + head];

    float m = -1e30f, s = 0.f, a0 = 0.f, a1 = 0.f;
    int srcN = 0; float asvN = 0.f; float2 hvN = make_float2(0.f, 0.f);
    if (beg < end) {
        srcN = g_csrsrc[beg];
        asvN = __ldg(&g_as1[srcN * 4 + head]);
        hvN = *reinterpret_cast<const float2*>(&g_H1[srcN * 64 + ch]);
    }
    for (int p = beg; p < end; ++p) {
        float asv = asvN; float2 hv = hvN;
        if (p + 1 < end) {
            srcN = g_csrsrc[p + 1];
            asvN = __ldg(&g_as1[srcN * 4 + head]);
            hvN = *reinterpret_cast<const float2*>(&g_H1[srcN * 64 + ch]);
        }
        float e = asv + adv;
        e = (e > 0.f) ? e : 0.2f * e;
        float mn = fmaxf(m, e);
        float corr = __expf(m - mn);
        float w = __expf(e - mn);
        s = s * corr + w;
        a0 = a0 * corr + w * hv.x;
        a1 = a1 * corr + w * hv.y;
        m = mn;
    }
    float inv = 1.f / (s + 1e-16f);
    float o0 = a0 * inv + b1[ch];
    float o1 = a1 * inv + b1[ch + 1];
    o0 = (o0 > 0.f) ? o0 : expm1f(o0);   // elu
    o1 = (o1 > 0.f) ? o1 : expm1f(o1);
    *reinterpret_cast<float2*>(&g_X2[i * 64 + ch]) = make_float2(o0, o1);
}

// ---------------- GEMM 2: H2 = X2[N,64] @ W2[64,32] (+alpha epilogue) -------
__global__ void k_gemm2(const float* __restrict__ W2,
                        const float* __restrict__ a_src, const float* __restrict__ a_dst, int N) {
    __shared__ float Wsh[64 * 32];    // 8 KB
    __shared__ float xs[128][65];     // full 64-wide k, padded
    int t = threadIdx.x;
    int n0 = blockIdx.x * 128;
    for (int i = t; i < 64 * 32; i += 128) Wsh[i] = W2[i];
    for (int i = t; i < 128 * 64; i += 128) {
        int n = i >> 6, k = i & 63;
        int gn = n0 + n;
        xs[n][k] = (gn < N) ? g_X2[gn * 64 + k] : 0.f;
    }
    __syncthreads();
    int ng = t >> 2;   // 0..31 (4 nodes each)
    int cg = t & 3;    // 0..3 (8 cols each)
    float acc[4][8];
#pragma unroll
    for (int r = 0; r < 4; ++r)
#pragma unroll
        for (int j = 0; j < 8; ++j) acc[r][j] = 0.f;
#pragma unroll 4
    for (int k = 0; k < 64; ++k) {
        float wv[8];
#pragma unroll
        for (int j = 0; j < 8; ++j) wv[j] = Wsh[k * 32 + cg * 8 + j];
#pragma unroll
        for (int r = 0; r < 4; ++r) {
            float xv = xs[ng * 4 + r][k];
#pragma unroll
            for (int j = 0; j < 8; ++j) acc[r][j] = fmaf(xv, wv[j], acc[r][j]);
        }
    }

    float asw[8], adw[8];
#pragma unroll
    for (int j = 0; j < 8; ++j) { asw[j] = __ldg(&a_src[cg * 8 + j]); adw[j] = __ldg(&a_dst[cg * 8 + j]); }

#pragma unroll
    for (int r = 0; r < 4; ++r) {
        int gn = n0 + ng * 4 + r;
        float ps = 0.f, pd = 0.f;
#pragma unroll
        for (int j = 0; j < 8; ++j) { ps = fmaf(acc[r][j], asw[j], ps); pd = fmaf(acc[r][j], adw[j], pd); }
        // reduce across the 4 col-groups of this node (lanes ng*4 .. ng*4+3)
        ps += __shfl_xor_sync(0xffffffffu, ps, 1);
        pd += __shfl_xor_sync(0xffffffffu, pd, 1);
        ps += __shfl_xor_sync(0xffffffffu, ps, 2);
        pd += __shfl_xor_sync(0xffffffffu, pd, 2);
        if (gn < N) {
            float4* dst = reinterpret_cast<float4*>(&g_H2[gn * 32 + cg * 8]);
            dst[0] = make_float4(acc[r][0], acc[r][1], acc[r][2], acc[r][3]);
            dst[1] = make_float4(acc[r][4], acc[r][5], acc[r][6], acc[r][7]);
            if (cg == 0) { g_as2[gn] = ps; g_ad2[gn] = pd; }
        }
    }
}

// ---------------- layer-2 aggregation: warp/node, 1 head, 32 channels -------
__global__ void k_agg2(const float* __restrict__ b2, float* __restrict__ out, int N) {
    int gw = (blockIdx.x * blockDim.x + threadIdx.x) >> 5;
    if (gw >= N) return;
    int lane = threadIdx.x & 31;
    int i = gw;
    int beg = g_rowptr[i], end = g_rowptr[i + 1];
    float adv = g_ad2[i];

    float m = -1e30f, s = 0.f, a = 0.f;
    int srcN = 0; float asvN = 0.f; float hvN = 0.f;
    if (beg < end) {
        srcN = g_csrsrc[beg];
        asvN = __ldg(&g_as2[srcN]);
        hvN = g_H2[srcN * 32 + lane];
    }
    for (int p = beg; p < end; ++p) {
        float asv = asvN; float hv = hvN;
        if (p + 1 < end) {
            srcN = g_csrsrc[p + 1];
            asvN = __ldg(&g_as2[srcN]);
            hvN = g_H2[srcN * 32 + lane];
        }
        float e = asv + adv;
        e = (e > 0.f) ? e : 0.2f * e;
        float mn = fmaxf(m, e);
        float corr = __expf(m - mn);
        float w = __expf(e - mn);
        s = s * corr + w;
        a = a * corr + w * hv;
        m = mn;
    }
    float inv = 1.f / (s + 1e-16f);
    out[i * 32 + lane] = a * inv + b2[lane];
}

// ---------------- launch -----------------------------------------------------
extern "C" void kernel_launch(void* const* d_in, const int* in_sizes, int n_in,
                              void* d_out, int out_size) {
    const float* x      = (const float*)d_in[0];
    const int*   ei     = (const int*)  d_in[1];
    const float* W1     = (const float*)d_in[2];
    const float* a_src1 = (const float*)d_in[3];
    const float* a_dst1 = (const float*)d_in[4];
    const float* b1     = (const float*)d_in[5];
    const float* W2     = (const float*)d_in[6];
    const float* a_src2 = (const float*)d_in[7];
    const float* a_dst2 = (const float*)d_in[8];
    const float* b2     = (const float*)d_in[9];

    int N = in_sizes[0] / 128;
    int E = in_sizes[1] / 2;
    int nb = (N + 1023) / 1024;

    int gemmBlocks = (N + 127) / 128;
    int histBlocks = 1184;

    // L1: GEMM1(+alphas1) overlapped with edge histogram (independent work)
    k_gemm1_hist<<<gemmBlocks + histBlocks, 256>>>(x, W1, a_src1, a_dst1, ei, N, E, gemmBlocks);
    // CSR scan + fill
    k_scan_block<<<nb, 1024>>>(N);
    k_scan_sums<<<1, 32>>>(nb);
    k_scan_add<<<nb, 1024>>>(N);      // also resets g_deg for the next replay
    k_fill<<<(E + 255) / 256, 256>>>(ei, E);
    // layer 1 aggregation (+elu)
    k_agg1<<<(N * 32 + 255) / 256, 256>>>(b1, N);
    // layer 2
    k_gemm2<<<(N + 127) / 128, 128>>>(W2, a_src2, a_dst2, N);
    k_agg2<<<(N * 32 + 255) / 256, 256>>>(b2, (float*)d_out, N);
}